// round 10
// baseline (speedup 1.0000x reference)
#include <cuda_runtime.h>
#include <cuda_fp16.h>
#include <cstdint>
#include <cstddef>

// ---------------------------------------------------------------------------
// MHSA B=1024 S=64 D=1024 H=16 dk=64.
// R10: fp16 m16n8k16. GEMM: BK=64 + SW128 swizzle (conflict-free cp.async
// writes AND ldmatrix reads), 1 sync/chunk, 2-stage 64KB dynamic smem.
// Attention: register-resident softmax (unchanged from R9).
// ---------------------------------------------------------------------------

#define M_TOT   65536
#define DM      1024
#define SEQ     64
#define DK      64

__device__ __half g_xh[(size_t)M_TOT * DM];
__device__ __half g_wh[(size_t)4 * DM * DM];      // fp16 W^T: [mat][n][k]
__device__ __half g_qh[(size_t)M_TOT * DM];
__device__ __half g_kh[(size_t)M_TOT * DM];
__device__ __half g_vh[(size_t)M_TOT * DM];
__device__ __half g_ch[(size_t)M_TOT * DM];

// ---------------- PTX helpers ----------------
__device__ __forceinline__ void mma_f16(float* d, const uint32_t* a, const uint32_t* b) {
    asm volatile(
        "mma.sync.aligned.m16n8k16.row.col.f32.f16.f16.f32 "
        "{%0,%1,%2,%3}, {%4,%5,%6,%7}, {%8,%9}, {%0,%1,%2,%3};"
        : "+f"(d[0]), "+f"(d[1]), "+f"(d[2]), "+f"(d[3])
        : "r"(a[0]), "r"(a[1]), "r"(a[2]), "r"(a[3]), "r"(b[0]), "r"(b[1]));
}
__device__ __forceinline__ void ldsm4(uint32_t* r, uint32_t a) {
    asm volatile("ldmatrix.sync.aligned.m8n8.x4.shared.b16 {%0,%1,%2,%3}, [%4];"
                 : "=r"(r[0]), "=r"(r[1]), "=r"(r[2]), "=r"(r[3]) : "r"(a));
}
__device__ __forceinline__ void ldsm4t(uint32_t* r, uint32_t a) {
    asm volatile("ldmatrix.sync.aligned.m8n8.x4.trans.shared.b16 {%0,%1,%2,%3}, [%4];"
                 : "=r"(r[0]), "=r"(r[1]), "=r"(r[2]), "=r"(r[3]) : "r"(a));
}
__device__ __forceinline__ void cp16(uint32_t s, const void* g) {
    asm volatile("cp.async.ca.shared.global [%0], [%1], 16;" :: "r"(s), "l"(g));
}
__device__ __forceinline__ void cp_commit() { asm volatile("cp.async.commit_group;"); }
__device__ __forceinline__ void cp_wait0()  { asm volatile("cp.async.wait_group 0;"); }
__device__ __forceinline__ uint32_t scvt(const void* p) {
    return (uint32_t)__cvta_generic_to_shared(p);
}

// ---------------- prepasses ----------------
__global__ __launch_bounds__(256) void half_x(const float* __restrict__ x) {
    const float4* src = (const float4*)x;
    uint2* dst = (uint2*)g_xh;
#pragma unroll
    for (int j = 0; j < 4; j++) {
        size_t i = (size_t)blockIdx.x * 1024 + j * 256 + threadIdx.x;
        float4 v = src[i];
        __half2 lo = __floats2half2_rn(v.x, v.y);
        __half2 hi = __floats2half2_rn(v.z, v.w);
        uint2 o;
        o.x = *(uint32_t*)&lo;
        o.y = *(uint32_t*)&hi;
        dst[i] = o;
    }
}

__global__ void half_wT(const float* __restrict__ Wq, const float* __restrict__ Wk,
                        const float* __restrict__ Wv, const float* __restrict__ Wo)
{
    __shared__ __half t[32][33];
    const int z = blockIdx.z;
    const float* src = (z == 0) ? Wq : (z == 1) ? Wk : (z == 2) ? Wv : Wo;
    __half* dst = g_wh + (size_t)z * DM * DM;
    const int tx = threadIdx.x, ty = threadIdx.y;
    const int bx = blockIdx.x * 32, by = blockIdx.y * 32;
#pragma unroll
    for (int j = 0; j < 4; j++)
        t[ty + 8 * j][tx] = __float2half(src[(size_t)(by + ty + 8 * j) * DM + bx + tx]);
    __syncthreads();
#pragma unroll
    for (int j = 0; j < 4; j++)
        dst[(size_t)(bx + ty + 8 * j) * DM + by + tx] = t[tx][ty + 8 * j];
}

// ---------------- GEMM: C[128x128] = A[.,1024] @ W^T[n][k] + bias ----------
// 128 threads = 4 warps (2m x 2n), warp tile 64x64. BK=64 -> 128B rows with
// SW128 swizzle: conflict-free cp.async stores and ldmatrix loads.
// 2-stage dynamic smem: [s0 A 16K][s0 B 16K][s1 A][s1 B] = 64KB.
#define MATB 16384           // bytes per matrix per stage
#define STAGEB 32768

template <bool HALF_OUT>
__device__ __forceinline__ void gemm_body(
    const __half* __restrict__ A, const __half* __restrict__ Bt,
    const float* __restrict__ bias, void* __restrict__ Cout,
    int bn, int bm)
{
    extern __shared__ __align__(16) __half smem[];
    const uint32_t sbase = scvt(smem);

    const int tid  = threadIdx.x;
    const int lane = tid & 31;
    const int warp = tid >> 5;
    const int wm = warp >> 1, wn = warp & 1;
    const int g  = lane >> 2, t = lane & 3;

    const __half* Ab = A + (size_t)bm * 128 * DM;
    const __half* Bb = Bt + (size_t)bn * 128 * DM;

    float acc[4][8][4];
#pragma unroll
    for (int i = 0; i < 4; i++)
#pragma unroll
        for (int j = 0; j < 8; j++)
#pragma unroll
            for (int r = 0; r < 4; r++) acc[i][j][r] = 0.f;

    // ldsm row/chunk decomposition (per-thread invariants)
    const int ra   = lane & 15;          // A: row within 16-row tile
    const int rsel = lane >> 4;          // A: 8-half chunk select
    const int bmi  = lane >> 3, br8 = lane & 7;
    const int rb   = (bmi >> 1) * 8 + br8;   // B: row within 16-row tile
    const int bcs  = bmi & 1;                // B: chunk select

    auto load_chunk = [&](int kc, int buf) {
        const uint32_t s0 = sbase + buf * STAGEB;
#pragma unroll
        for (int c = 0; c < 16; c++) {
            int id = tid + c * 128;            // 0..2047
            int half = id >> 10;               // 0 = A, 1 = B
            int l = id & 1023;
            int row = l >> 3, ch = l & 7;
            const __half* gp = (half ? Bb : Ab) + (size_t)row * DM + kc * 64 + ch * 8;
            uint32_t dst = s0 + half * MATB + row * 128 + ((ch ^ (row & 7)) << 4);
            cp16(dst, gp);
        }
        cp_commit();
    };

    load_chunk(0, 0);
#pragma unroll 1
    for (int kc = 0; kc < 16; kc++) {
        cp_wait0();
        __syncthreads();                      // single barrier per chunk
        if (kc < 15) load_chunk(kc + 1, (kc + 1) & 1);
        const uint32_t s0 = sbase + (kc & 1) * STAGEB;
#pragma unroll
        for (int ks = 0; ks < 4; ks++) {
            uint32_t af[4][4];
#pragma unroll
            for (int mt = 0; mt < 4; mt++) {
                int row = wm * 64 + mt * 16 + ra;
                ldsm4(af[mt], s0 + row * 128 + (((2 * ks + rsel) ^ (row & 7)) << 4));
            }
            uint32_t bf[4][4];
#pragma unroll
            for (int j = 0; j < 4; j++) {
                int row = wn * 64 + j * 16 + rb;
                ldsm4(bf[j], s0 + MATB + row * 128 + (((2 * ks + bcs) ^ (row & 7)) << 4));
            }
#pragma unroll
            for (int mt = 0; mt < 4; mt++)
#pragma unroll
                for (int nt = 0; nt < 8; nt++)
                    mma_f16(acc[mt][nt], af[mt], bf[nt >> 1] + (nt & 1) * 2);
        }
    }

#pragma unroll
    for (int mt = 0; mt < 4; mt++) {
        int r0 = bm * 128 + wm * 64 + mt * 16 + g;
#pragma unroll
        for (int nt = 0; nt < 8; nt++) {
            int c0 = bn * 128 + wn * 64 + nt * 8 + t * 2;
            float b0 = bias[c0], b1 = bias[c0 + 1];
            float v0 = acc[mt][nt][0] + b0;
            float v1 = acc[mt][nt][1] + b1;
            float v2 = acc[mt][nt][2] + b0;
            float v3 = acc[mt][nt][3] + b1;
            if (HALF_OUT) {
                __half* C = (__half*)Cout;
                *(__half2*)(C + (size_t)r0 * DM + c0)       = __floats2half2_rn(v0, v1);
                *(__half2*)(C + (size_t)(r0 + 8) * DM + c0) = __floats2half2_rn(v2, v3);
            } else {
                float* C = (float*)Cout;
                C[(size_t)r0 * DM + c0]           = v0;
                C[(size_t)r0 * DM + c0 + 1]       = v1;
                C[(size_t)(r0 + 8) * DM + c0]     = v2;
                C[(size_t)(r0 + 8) * DM + c0 + 1] = v3;
            }
        }
    }
}

__global__ __launch_bounds__(128) void qkv_gemm(
    const float* __restrict__ bq, const float* __restrict__ bk, const float* __restrict__ bv)
{
    int which = blockIdx.x >> 3;
    int bn = blockIdx.x & 7;
    const __half* W = g_wh + (size_t)which * DM * DM;
    const float* b = (which == 0) ? bq : (which == 1) ? bk : bv;
    __half* C = (which == 0) ? g_qh : (which == 1) ? g_kh : g_vh;
    gemm_body<true>(g_xh, W, b, C, bn, blockIdx.y);
}

__global__ __launch_bounds__(128) void out_gemm(
    const float* __restrict__ bo, float* __restrict__ out)
{
    gemm_body<false>(g_ch, g_wh + (size_t)3 * DM * DM, bo, out, blockIdx.x, blockIdx.y);
}

// ---------------- attention: one CTA (128 thr) per (b,h) ----------------
__device__ __forceinline__ float bias_at(int i, int j, const float* sBias) {
    int dr = (i >> 3) - (j >> 3) + 7;
    int df = (i & 7) - (j & 7) + 7;
    return sBias[dr * 15 + df];
}

#define AST 72   // half stride

__global__ __launch_bounds__(128, 5) void attn_kernel(const float* __restrict__ bias_table)
{
    __shared__ __align__(16) __half sQ[64 * AST];
    __shared__ __align__(16) __half sK[64 * AST];
    __shared__ __align__(16) __half sV[64 * AST];
    __shared__ float sBias[232];

    const int tid  = threadIdx.x;
    const int lane = tid & 31;
    const int warp = tid >> 5;
    const int g = lane >> 2, t = lane & 3;
    const int b = blockIdx.x >> 4, h = blockIdx.x & 15;

    const __half* qb = g_qh + (size_t)b * SEQ * DM + h * DK;
    const __half* kb = g_kh + (size_t)b * SEQ * DM + h * DK;
    const __half* vb = g_vh + (size_t)b * SEQ * DM + h * DK;

    for (int i = tid; i < 512; i += 128) {
        int s = i >> 3, c = i & 7;
        uint4 qv = ((const uint4*)(qb + (size_t)s * DM))[c];
        uint4 kv = ((const uint4*)(kb + (size_t)s * DM))[c];
        uint4 vv = ((const uint4*)(vb + (size_t)s * DM))[c];
        ((uint4*)(sQ + s * AST))[c] = qv;
        ((uint4*)(sK + s * AST))[c] = kv;
        ((uint4*)(sV + s * AST))[c] = vv;
    }
    for (int i = tid; i < 225; i += 128) sBias[i] = bias_table[i * 16 + h];
    __syncthreads();

    const uint32_t sQu = scvt(sQ), sKu = scvt(sK), sVu = scvt(sV);

    const uint32_t qBase = sQu + (uint32_t)(((warp * 16 + (lane & 15)) * AST + (lane >> 4) * 8) * 2);
    const int bmi = lane >> 3, br8 = lane & 7;
    const uint32_t kBase = sKu + (uint32_t)((((bmi >> 1) * 8 + br8) * AST + (bmi & 1) * 8) * 2);

    float acc[8][4];
#pragma unroll
    for (int nt = 0; nt < 8; nt++)
#pragma unroll
        for (int r = 0; r < 4; r++) acc[nt][r] = 0.f;

#pragma unroll
    for (int ks = 0; ks < 4; ks++) {
        uint32_t af[4];
        ldsm4(af, qBase + ks * 32);
#pragma unroll
        for (int j = 0; j < 4; j++) {
            uint32_t bf[4];
            ldsm4(bf, kBase + j * (16 * AST * 2) + ks * 32);
            mma_f16(acc[2 * j],     af, bf);
            mma_f16(acc[2 * j + 1], af, bf + 2);
        }
    }

    const float scale = 0.125f;
    const int i0 = warp * 16 + g;
    float mlo = -1e30f, mhi = -1e30f;
#pragma unroll
    for (int nt = 0; nt < 8; nt++) {
        int j0 = nt * 8 + t * 2;
        acc[nt][0] = acc[nt][0] * scale + bias_at(i0, j0, sBias);
        acc[nt][1] = acc[nt][1] * scale + bias_at(i0, j0 + 1, sBias);
        acc[nt][2] = acc[nt][2] * scale + bias_at(i0 + 8, j0, sBias);
        acc[nt][3] = acc[nt][3] * scale + bias_at(i0 + 8, j0 + 1, sBias);
        mlo = fmaxf(mlo, fmaxf(acc[nt][0], acc[nt][1]));
        mhi = fmaxf(mhi, fmaxf(acc[nt][2], acc[nt][3]));
    }
    mlo = fmaxf(mlo, __shfl_xor_sync(0xffffffffu, mlo, 1));
    mlo = fmaxf(mlo, __shfl_xor_sync(0xffffffffu, mlo, 2));
    mhi = fmaxf(mhi, __shfl_xor_sync(0xffffffffu, mhi, 1));
    mhi = fmaxf(mhi, __shfl_xor_sync(0xffffffffu, mhi, 2));
    float slo = 0.f, shi = 0.f;
#pragma unroll
    for (int nt = 0; nt < 8; nt++) {
        acc[nt][0] = __expf(acc[nt][0] - mlo);
        acc[nt][1] = __expf(acc[nt][1] - mlo);
        acc[nt][2] = __expf(acc[nt][2] - mhi);
        acc[nt][3] = __expf(acc[nt][3] - mhi);
        slo += acc[nt][0] + acc[nt][1];
        shi += acc[nt][2] + acc[nt][3];
    }
    slo += __shfl_xor_sync(0xffffffffu, slo, 1);
    slo += __shfl_xor_sync(0xffffffffu, slo, 2);
    shi += __shfl_xor_sync(0xffffffffu, shi, 1);
    shi += __shfl_xor_sync(0xffffffffu, shi, 2);
    const float ilo = 1.f / slo, ihi = 1.f / shi;

    uint32_t plo[8], phi[8];
#pragma unroll
    for (int nt = 0; nt < 8; nt++) {
        __half2 hl = __floats2half2_rn(acc[nt][0] * ilo, acc[nt][1] * ilo);
        __half2 hh = __floats2half2_rn(acc[nt][2] * ihi, acc[nt][3] * ihi);
        plo[nt] = *(uint32_t*)&hl;
        phi[nt] = *(uint32_t*)&hh;
    }

    __half* cb = g_ch + (size_t)b * SEQ * DM + h * DK;
#pragma unroll
    for (int nt = 0; nt < 8; nt++) {
        uint32_t v01[4], v23[4];
        ldsm4t(v01, sVu + (uint32_t)(((lane) * AST + nt * 8) * 2));
        ldsm4t(v23, sVu + (uint32_t)(((32 + lane) * AST + nt * 8) * 2));
        float o[4] = {0.f, 0.f, 0.f, 0.f};
#pragma unroll
        for (int ks = 0; ks < 4; ks++) {
            uint32_t af[4] = {plo[2 * ks], phi[2 * ks], plo[2 * ks + 1], phi[2 * ks + 1]};
            const uint32_t* bf = (ks < 2) ? (v01 + ks * 2) : (v23 + (ks - 2) * 2);
            mma_f16(o, af, bf);
        }
        int d0 = nt * 8 + t * 2;
        *(__half2*)(cb + (size_t)i0 * DM + d0)       = __floats2half2_rn(o[0], o[1]);
        *(__half2*)(cb + (size_t)(i0 + 8) * DM + d0) = __floats2half2_rn(o[2], o[3]);
    }
}

// ---------------- launch ----------------
extern "C" void kernel_launch(void* const* d_in, const int* in_sizes, int n_in,
                              void* d_out, int out_size)
{
    const float* x  = (const float*)d_in[0];
    const float* Wq = (const float*)d_in[1];
    const float* bq = (const float*)d_in[2];
    const float* Wk = (const float*)d_in[3];
    const float* bk = (const float*)d_in[4];
    const float* Wv = (const float*)d_in[5];
    const float* bv = (const float*)d_in[6];
    const float* Wo = (const float*)d_in[7];
    const float* bo = (const float*)d_in[8];
    const float* bt = (const float*)d_in[9];
    float* out = (float*)d_out;

    cudaFuncSetAttribute(qkv_gemm, cudaFuncAttributeMaxDynamicSharedMemorySize, 2 * STAGEB);
    cudaFuncSetAttribute(out_gemm, cudaFuncAttributeMaxDynamicSharedMemorySize, 2 * STAGEB);

    half_x<<<16384, 256>>>(x);
    half_wT<<<dim3(32, 32, 4), dim3(32, 8)>>>(Wq, Wk, Wv, Wo);
    qkv_gemm<<<dim3(24, 512), 128, 2 * STAGEB>>>(bq, bk, bv);
    attn_kernel<<<16384, 128>>>(bt);
    out_gemm<<<dim3(8, 512), 128, 2 * STAGEB>>>(bo, out);
}

// round 12
// speedup vs baseline: 1.1978x; 1.1978x over previous
#include <cuda_runtime.h>
#include <cuda_fp16.h>
#include <cstdint>
#include <cstddef>

// ---------------------------------------------------------------------------
// MHSA B=1024 S=64 D=1024 H=16 dk=64.
// R12: R11 (256x128 CTA tile, 8 warps of 64x64, fp16 m16n8k16) with the
// A-tile loader fixed: 1536 16B chunks/stage -> 6 cp.async per thread
// (R11 only issued 3, leaving A rows 128..255 uninitialized -> NaN).
// Attention: R9 register-softmax kernel, unchanged.
// ---------------------------------------------------------------------------

#define M_TOT   65536
#define DM      1024
#define SEQ     64
#define DK      64

__device__ __half g_xh[(size_t)M_TOT * DM];
__device__ __half g_wh[(size_t)4 * DM * DM];      // fp16 W^T: [mat][n][k]
__device__ __half g_qh[(size_t)M_TOT * DM];
__device__ __half g_kh[(size_t)M_TOT * DM];
__device__ __half g_vh[(size_t)M_TOT * DM];
__device__ __half g_ch[(size_t)M_TOT * DM];

// ---------------- PTX helpers ----------------
__device__ __forceinline__ void mma_f16(float* d, const uint32_t* a, const uint32_t* b) {
    asm volatile(
        "mma.sync.aligned.m16n8k16.row.col.f32.f16.f16.f32 "
        "{%0,%1,%2,%3}, {%4,%5,%6,%7}, {%8,%9}, {%0,%1,%2,%3};"
        : "+f"(d[0]), "+f"(d[1]), "+f"(d[2]), "+f"(d[3])
        : "r"(a[0]), "r"(a[1]), "r"(a[2]), "r"(a[3]), "r"(b[0]), "r"(b[1]));
}
__device__ __forceinline__ void ldsm4(uint32_t* r, uint32_t a) {
    asm volatile("ldmatrix.sync.aligned.m8n8.x4.shared.b16 {%0,%1,%2,%3}, [%4];"
                 : "=r"(r[0]), "=r"(r[1]), "=r"(r[2]), "=r"(r[3]) : "r"(a));
}
__device__ __forceinline__ void ldsm4t(uint32_t* r, uint32_t a) {
    asm volatile("ldmatrix.sync.aligned.m8n8.x4.trans.shared.b16 {%0,%1,%2,%3}, [%4];"
                 : "=r"(r[0]), "=r"(r[1]), "=r"(r[2]), "=r"(r[3]) : "r"(a));
}
__device__ __forceinline__ void cp16(uint32_t s, const void* g) {
    asm volatile("cp.async.ca.shared.global [%0], [%1], 16;" :: "r"(s), "l"(g));
}
__device__ __forceinline__ void cp_commit() { asm volatile("cp.async.commit_group;"); }
__device__ __forceinline__ void cp_wait0()  { asm volatile("cp.async.wait_group 0;"); }
__device__ __forceinline__ uint32_t scvt(const void* p) {
    return (uint32_t)__cvta_generic_to_shared(p);
}

// ---------------- prepasses ----------------
__global__ __launch_bounds__(256) void half_x(const float* __restrict__ x) {
    const float4* src = (const float4*)x;
    uint2* dst = (uint2*)g_xh;
#pragma unroll
    for (int j = 0; j < 4; j++) {
        size_t i = (size_t)blockIdx.x * 1024 + j * 256 + threadIdx.x;
        float4 v = src[i];
        __half2 lo = __floats2half2_rn(v.x, v.y);
        __half2 hi = __floats2half2_rn(v.z, v.w);
        uint2 o;
        o.x = *(uint32_t*)&lo;
        o.y = *(uint32_t*)&hi;
        dst[i] = o;
    }
}

__global__ void half_wT(const float* __restrict__ Wq, const float* __restrict__ Wk,
                        const float* __restrict__ Wv, const float* __restrict__ Wo)
{
    __shared__ __half t[32][33];
    const int z = blockIdx.z;
    const float* src = (z == 0) ? Wq : (z == 1) ? Wk : (z == 2) ? Wv : Wo;
    __half* dst = g_wh + (size_t)z * DM * DM;
    const int tx = threadIdx.x, ty = threadIdx.y;
    const int bx = blockIdx.x * 32, by = blockIdx.y * 32;
#pragma unroll
    for (int j = 0; j < 4; j++)
        t[ty + 8 * j][tx] = __float2half(src[(size_t)(by + ty + 8 * j) * DM + bx + tx]);
    __syncthreads();
#pragma unroll
    for (int j = 0; j < 4; j++)
        dst[(size_t)(bx + ty + 8 * j) * DM + by + tx] = t[tx][ty + 8 * j];
}

// ---------------- GEMM: C[256x128] = A[.,1024] @ W^T[n][k] + bias ----------
// 256 threads = 8 warps (4m x 2n), warp tile 64x64, BK=32.
// smem stride 40 halves. Dynamic smem 61440B:
//   [A stage0 20480B][A stage1 20480B][B stage0 10240B][B stage1 10240B]
#define GST    40
#define A_STGB 20480
#define B_STGB 10240
#define B_OFF  40960
#define GEMM_SMEM 61440

template <bool HALF_OUT>
__device__ __forceinline__ void gemm_body(
    const __half* __restrict__ A, const __half* __restrict__ Bt,
    const float* __restrict__ bias, void* __restrict__ Cout,
    int bn, int bm)
{
    extern __shared__ __align__(16) __half smem[];
    const uint32_t sbase = scvt(smem);

    const int tid  = threadIdx.x;
    const int lane = tid & 31;
    const int warp = tid >> 5;
    const int wm = warp >> 1, wn = warp & 1;
    const int g  = lane >> 2, t = lane & 3;

    const __half* Ab = A + (size_t)bm * 256 * DM;
    const __half* Bb = Bt + (size_t)bn * 128 * DM;

    float acc[4][8][4];
#pragma unroll
    for (int i = 0; i < 4; i++)
#pragma unroll
        for (int j = 0; j < 8; j++)
#pragma unroll
            for (int r = 0; r < 4; r++) acc[i][j][r] = 0.f;

    // ldsm per-thread address invariants (R9 mapping)
    const uint32_t aBase = sbase +
        (uint32_t)(((wm * 64 + (lane & 15)) * GST + (lane >> 4) * 8) * 2);
    const int bmi = lane >> 3, br8 = lane & 7;
    const uint32_t bBase = sbase + B_OFF +
        (uint32_t)(((wn * 64 + (bmi >> 1) * 8 + br8) * GST + (bmi & 1) * 8) * 2);

    auto load_chunk = [&](int kc, int buf) {
        const uint32_t aS = sbase + buf * A_STGB;
        const uint32_t bS = sbase + B_OFF + buf * B_STGB;
        // A: 256 rows x 32 halves = 1024 x16B chunks; B: 128 x 32 = 512 chunks.
        // 1536 total -> 6 per thread (c=0..3 statically A, c=4..5 statically B).
#pragma unroll
        for (int c = 0; c < 6; c++) {
            int id = tid + c * 256;                 // 0..1535
            if (id < 1024) {
                int row = id >> 2, c8 = (id & 3) * 8;
                cp16(aS + (uint32_t)((row * GST + c8) * 2),
                     Ab + (size_t)row * DM + kc * 32 + c8);
            } else {
                int l = id - 1024;
                int row = l >> 2, c8 = (l & 3) * 8;
                cp16(bS + (uint32_t)((row * GST + c8) * 2),
                     Bb + (size_t)row * DM + kc * 32 + c8);
            }
        }
        cp_commit();
    };

    load_chunk(0, 0);
#pragma unroll 1
    for (int kc = 0; kc < 32; kc++) {
        cp_wait0();
        __syncthreads();
        if (kc < 31) load_chunk(kc + 1, (kc + 1) & 1);
        const uint32_t bufA = (kc & 1) * A_STGB;
        const uint32_t bufB = (kc & 1) * B_STGB;
#pragma unroll
        for (int ks = 0; ks < 2; ks++) {
            uint32_t af[4][4];
#pragma unroll
            for (int mt = 0; mt < 4; mt++)
                ldsm4(af[mt], aBase + bufA + mt * (16 * GST * 2) + ks * 32);
            uint32_t bf[4][4];
#pragma unroll
            for (int j = 0; j < 4; j++)
                ldsm4(bf[j], bBase + bufB + j * (16 * GST * 2) + ks * 32);
#pragma unroll
            for (int mt = 0; mt < 4; mt++)
#pragma unroll
                for (int nt = 0; nt < 8; nt++)
                    mma_f16(acc[mt][nt], af[mt], bf[nt >> 1] + (nt & 1) * 2);
        }
        __syncthreads();
    }

#pragma unroll
    for (int mt = 0; mt < 4; mt++) {
        int r0 = bm * 256 + wm * 64 + mt * 16 + g;
#pragma unroll
        for (int nt = 0; nt < 8; nt++) {
            int c0 = bn * 128 + wn * 64 + nt * 8 + t * 2;
            float b0 = bias[c0], b1 = bias[c0 + 1];
            float v0 = acc[mt][nt][0] + b0;
            float v1 = acc[mt][nt][1] + b1;
            float v2 = acc[mt][nt][2] + b0;
            float v3 = acc[mt][nt][3] + b1;
            if (HALF_OUT) {
                __half* C = (__half*)Cout;
                *(__half2*)(C + (size_t)r0 * DM + c0)       = __floats2half2_rn(v0, v1);
                *(__half2*)(C + (size_t)(r0 + 8) * DM + c0) = __floats2half2_rn(v2, v3);
            } else {
                float* C = (float*)Cout;
                C[(size_t)r0 * DM + c0]           = v0;
                C[(size_t)r0 * DM + c0 + 1]       = v1;
                C[(size_t)(r0 + 8) * DM + c0]     = v2;
                C[(size_t)(r0 + 8) * DM + c0 + 1] = v3;
            }
        }
    }
}

__global__ __launch_bounds__(256, 1) void qkv_gemm(
    const float* __restrict__ bq, const float* __restrict__ bk, const float* __restrict__ bv)
{
    int which = blockIdx.x >> 3;
    int bn = blockIdx.x & 7;
    const __half* W = g_wh + (size_t)which * DM * DM;
    const float* b = (which == 0) ? bq : (which == 1) ? bk : bv;
    __half* C = (which == 0) ? g_qh : (which == 1) ? g_kh : g_vh;
    gemm_body<true>(g_xh, W, b, C, bn, blockIdx.y);
}

__global__ __launch_bounds__(256, 1) void out_gemm(
    const float* __restrict__ bo, float* __restrict__ out)
{
    gemm_body<false>(g_ch, g_wh + (size_t)3 * DM * DM, bo, out, blockIdx.x, blockIdx.y);
}

// ---------------- attention: one CTA (128 thr) per (b,h) — R9 verbatim ----
__device__ __forceinline__ float bias_at(int i, int j, const float* sBias) {
    int dr = (i >> 3) - (j >> 3) + 7;
    int df = (i & 7) - (j & 7) + 7;
    return sBias[dr * 15 + df];
}

#define AST 72   // half stride

__global__ __launch_bounds__(128, 5) void attn_kernel(const float* __restrict__ bias_table)
{
    __shared__ __align__(16) __half sQ[64 * AST];
    __shared__ __align__(16) __half sK[64 * AST];
    __shared__ __align__(16) __half sV[64 * AST];
    __shared__ float sBias[232];

    const int tid  = threadIdx.x;
    const int lane = tid & 31;
    const int warp = tid >> 5;
    const int g = lane >> 2, t = lane & 3;
    const int b = blockIdx.x >> 4, h = blockIdx.x & 15;

    const __half* qb = g_qh + (size_t)b * SEQ * DM + h * DK;
    const __half* kb = g_kh + (size_t)b * SEQ * DM + h * DK;
    const __half* vb = g_vh + (size_t)b * SEQ * DM + h * DK;

    for (int i = tid; i < 512; i += 128) {
        int s = i >> 3, c = i & 7;
        uint4 qv = ((const uint4*)(qb + (size_t)s * DM))[c];
        uint4 kv = ((const uint4*)(kb + (size_t)s * DM))[c];
        uint4 vv = ((const uint4*)(vb + (size_t)s * DM))[c];
        ((uint4*)(sQ + s * AST))[c] = qv;
        ((uint4*)(sK + s * AST))[c] = kv;
        ((uint4*)(sV + s * AST))[c] = vv;
    }
    for (int i = tid; i < 225; i += 128) sBias[i] = bias_table[i * 16 + h];
    __syncthreads();

    const uint32_t sQu = scvt(sQ), sKu = scvt(sK), sVu = scvt(sV);

    const uint32_t qBase = sQu + (uint32_t)(((warp * 16 + (lane & 15)) * AST + (lane >> 4) * 8) * 2);
    const int bmi = lane >> 3, br8 = lane & 7;
    const uint32_t kBase = sKu + (uint32_t)((((bmi >> 1) * 8 + br8) * AST + (bmi & 1) * 8) * 2);

    float acc[8][4];
#pragma unroll
    for (int nt = 0; nt < 8; nt++)
#pragma unroll
        for (int r = 0; r < 4; r++) acc[nt][r] = 0.f;

#pragma unroll
    for (int ks = 0; ks < 4; ks++) {
        uint32_t af[4];
        ldsm4(af, qBase + ks * 32);
#pragma unroll
        for (int j = 0; j < 4; j++) {
            uint32_t bf[4];
            ldsm4(bf, kBase + j * (16 * AST * 2) + ks * 32);
            mma_f16(acc[2 * j],     af, bf);
            mma_f16(acc[2 * j + 1], af, bf + 2);
        }
    }

    const float scale = 0.125f;
    const int i0 = warp * 16 + g;
    float mlo = -1e30f, mhi = -1e30f;
#pragma unroll
    for (int nt = 0; nt < 8; nt++) {
        int j0 = nt * 8 + t * 2;
        acc[nt][0] = acc[nt][0] * scale + bias_at(i0, j0, sBias);
        acc[nt][1] = acc[nt][1] * scale + bias_at(i0, j0 + 1, sBias);
        acc[nt][2] = acc[nt][2] * scale + bias_at(i0 + 8, j0, sBias);
        acc[nt][3] = acc[nt][3] * scale + bias_at(i0 + 8, j0 + 1, sBias);
        mlo = fmaxf(mlo, fmaxf(acc[nt][0], acc[nt][1]));
        mhi = fmaxf(mhi, fmaxf(acc[nt][2], acc[nt][3]));
    }
    mlo = fmaxf(mlo, __shfl_xor_sync(0xffffffffu, mlo, 1));
    mlo = fmaxf(mlo, __shfl_xor_sync(0xffffffffu, mlo, 2));
    mhi = fmaxf(mhi, __shfl_xor_sync(0xffffffffu, mhi, 1));
    mhi = fmaxf(mhi, __shfl_xor_sync(0xffffffffu, mhi, 2));
    float slo = 0.f, shi = 0.f;
#pragma unroll
    for (int nt = 0; nt < 8; nt++) {
        acc[nt][0] = __expf(acc[nt][0] - mlo);
        acc[nt][1] = __expf(acc[nt][1] - mlo);
        acc[nt][2] = __expf(acc[nt][2] - mhi);
        acc[nt][3] = __expf(acc[nt][3] - mhi);
        slo += acc[nt][0] + acc[nt][1];
        shi += acc[nt][2] + acc[nt][3];
    }
    slo += __shfl_xor_sync(0xffffffffu, slo, 1);
    slo += __shfl_xor_sync(0xffffffffu, slo, 2);
    shi += __shfl_xor_sync(0xffffffffu, shi, 1);
    shi += __shfl_xor_sync(0xffffffffu, shi, 2);
    const float ilo = 1.f / slo, ihi = 1.f / shi;

    uint32_t plo[8], phi[8];
#pragma unroll
    for (int nt = 0; nt < 8; nt++) {
        __half2 hl = __floats2half2_rn(acc[nt][0] * ilo, acc[nt][1] * ilo);
        __half2 hh = __floats2half2_rn(acc[nt][2] * ihi, acc[nt][3] * ihi);
        plo[nt] = *(uint32_t*)&hl;
        phi[nt] = *(uint32_t*)&hh;
    }

    __half* cb = g_ch + (size_t)b * SEQ * DM + h * DK;
#pragma unroll
    for (int nt = 0; nt < 8; nt++) {
        uint32_t v01[4], v23[4];
        ldsm4t(v01, sVu + (uint32_t)(((lane) * AST + nt * 8) * 2));
        ldsm4t(v23, sVu + (uint32_t)(((32 + lane) * AST + nt * 8) * 2));
        float o[4] = {0.f, 0.f, 0.f, 0.f};
#pragma unroll
        for (int ks = 0; ks < 4; ks++) {
            uint32_t af[4] = {plo[2 * ks], phi[2 * ks], plo[2 * ks + 1], phi[2 * ks + 1]};
            const uint32_t* bf = (ks < 2) ? (v01 + ks * 2) : (v23 + (ks - 2) * 2);
            mma_f16(o, af, bf);
        }
        int d0 = nt * 8 + t * 2;
        *(__half2*)(cb + (size_t)i0 * DM + d0)       = __floats2half2_rn(o[0], o[1]);
        *(__half2*)(cb + (size_t)(i0 + 8) * DM + d0) = __floats2half2_rn(o[2], o[3]);
    }
}

// ---------------- launch ----------------
extern "C" void kernel_launch(void* const* d_in, const int* in_sizes, int n_in,
                              void* d_out, int out_size)
{
    const float* x  = (const float*)d_in[0];
    const float* Wq = (const float*)d_in[1];
    const float* bq = (const float*)d_in[2];
    const float* Wk = (const float*)d_in[3];
    const float* bk = (const float*)d_in[4];
    const float* Wv = (const float*)d_in[5];
    const float* bv = (const float*)d_in[6];
    const float* Wo = (const float*)d_in[7];
    const float* bo = (const float*)d_in[8];
    const float* bt = (const float*)d_in[9];
    float* out = (float*)d_out;

    cudaFuncSetAttribute(qkv_gemm, cudaFuncAttributeMaxDynamicSharedMemorySize, GEMM_SMEM);
    cudaFuncSetAttribute(out_gemm, cudaFuncAttributeMaxDynamicSharedMemorySize, GEMM_SMEM);

    half_x<<<16384, 256>>>(x);
    half_wT<<<dim3(32, 32, 4), dim3(32, 8)>>>(Wq, Wk, Wv, Wo);
    qkv_gemm<<<dim3(24, 256), 256, GEMM_SMEM>>>(bq, bk, bv);
    attn_kernel<<<16384, 128>>>(bt);
    out_gemm<<<dim3(8, 256), 256, GEMM_SMEM>>>(bo, out);
}

// round 14
// speedup vs baseline: 1.4151x; 1.1814x over previous
#include <cuda_runtime.h>
#include <cuda_fp16.h>
#include <cstdint>
#include <cstddef>

// ---------------------------------------------------------------------------
// MHSA B=1024 S=64 D=1024 H=16 dk=64.
// R14: R13 (128x128 CTA, 4 warps of 64x64, fp16 m16n8k16, 3-stage cp.async
// pipeline, wait_group 1, one sync/chunk) with the stage loader FIXED:
// each stage needs 1024 x 16B chunks (512 A + 512 B) -> 8 cp.async/thread.
// R13 issued only 4, leaving rows 64..127 of A and B uninitialized -> NaN.
// Attention: R9 register-softmax kernel, unchanged.
// ---------------------------------------------------------------------------

#define M_TOT   65536
#define DM      1024
#define SEQ     64
#define DK      64

__device__ __half g_xh[(size_t)M_TOT * DM];
__device__ __half g_wh[(size_t)4 * DM * DM];      // fp16 W^T: [mat][n][k]
__device__ __half g_qh[(size_t)M_TOT * DM];
__device__ __half g_kh[(size_t)M_TOT * DM];
__device__ __half g_vh[(size_t)M_TOT * DM];
__device__ __half g_ch[(size_t)M_TOT * DM];

// ---------------- PTX helpers ----------------
__device__ __forceinline__ void mma_f16(float* d, const uint32_t* a, const uint32_t* b) {
    asm volatile(
        "mma.sync.aligned.m16n8k16.row.col.f32.f16.f16.f32 "
        "{%0,%1,%2,%3}, {%4,%5,%6,%7}, {%8,%9}, {%0,%1,%2,%3};"
        : "+f"(d[0]), "+f"(d[1]), "+f"(d[2]), "+f"(d[3])
        : "r"(a[0]), "r"(a[1]), "r"(a[2]), "r"(a[3]), "r"(b[0]), "r"(b[1]));
}
__device__ __forceinline__ void ldsm4(uint32_t* r, uint32_t a) {
    asm volatile("ldmatrix.sync.aligned.m8n8.x4.shared.b16 {%0,%1,%2,%3}, [%4];"
                 : "=r"(r[0]), "=r"(r[1]), "=r"(r[2]), "=r"(r[3]) : "r"(a));
}
__device__ __forceinline__ void ldsm4t(uint32_t* r, uint32_t a) {
    asm volatile("ldmatrix.sync.aligned.m8n8.x4.trans.shared.b16 {%0,%1,%2,%3}, [%4];"
                 : "=r"(r[0]), "=r"(r[1]), "=r"(r[2]), "=r"(r[3]) : "r"(a));
}
__device__ __forceinline__ void cp16(uint32_t s, const void* g) {
    asm volatile("cp.async.ca.shared.global [%0], [%1], 16;" :: "r"(s), "l"(g));
}
__device__ __forceinline__ void cp_commit() { asm volatile("cp.async.commit_group;"); }
__device__ __forceinline__ void cp_wait0()  { asm volatile("cp.async.wait_group 0;"); }
__device__ __forceinline__ void cp_wait1()  { asm volatile("cp.async.wait_group 1;"); }
__device__ __forceinline__ uint32_t scvt(const void* p) {
    return (uint32_t)__cvta_generic_to_shared(p);
}

// ---------------- prepasses ----------------
__global__ __launch_bounds__(256) void half_x(const float* __restrict__ x) {
    const float4* src = (const float4*)x;
    uint2* dst = (uint2*)g_xh;
#pragma unroll
    for (int j = 0; j < 4; j++) {
        size_t i = (size_t)blockIdx.x * 1024 + j * 256 + threadIdx.x;
        float4 v = src[i];
        __half2 lo = __floats2half2_rn(v.x, v.y);
        __half2 hi = __floats2half2_rn(v.z, v.w);
        uint2 o;
        o.x = *(uint32_t*)&lo;
        o.y = *(uint32_t*)&hi;
        dst[i] = o;
    }
}

__global__ void half_wT(const float* __restrict__ Wq, const float* __restrict__ Wk,
                        const float* __restrict__ Wv, const float* __restrict__ Wo)
{
    __shared__ __half t[32][33];
    const int z = blockIdx.z;
    const float* src = (z == 0) ? Wq : (z == 1) ? Wk : (z == 2) ? Wv : Wo;
    __half* dst = g_wh + (size_t)z * DM * DM;
    const int tx = threadIdx.x, ty = threadIdx.y;
    const int bx = blockIdx.x * 32, by = blockIdx.y * 32;
#pragma unroll
    for (int j = 0; j < 4; j++)
        t[ty + 8 * j][tx] = __float2half(src[(size_t)(by + ty + 8 * j) * DM + bx + tx]);
    __syncthreads();
#pragma unroll
    for (int j = 0; j < 4; j++)
        dst[(size_t)(bx + ty + 8 * j) * DM + by + tx] = t[tx][ty + 8 * j];
}

// ---------------- GEMM: C[128x128] = A[.,1024] @ W^T[n][k] + bias ----------
// 128 threads = 4 warps (2m x 2n), warp tile 64x64, BK=32, stride 40 halves.
// 3-stage pipeline. Dynamic smem: 3 x [A 10240B | B 10240B] = 61440B.
#define GST    40
#define STG_B  20480           // bytes per stage (A 10240 + B 10240)
#define GEMM_SMEM 61440

template <bool HALF_OUT>
__device__ __forceinline__ void gemm_body(
    const __half* __restrict__ A, const __half* __restrict__ Bt,
    const float* __restrict__ bias, void* __restrict__ Cout,
    int bn, int bm)
{
    extern __shared__ __align__(16) __half smem[];
    const uint32_t sbase = scvt(smem);

    const int tid  = threadIdx.x;
    const int lane = tid & 31;
    const int warp = tid >> 5;
    const int wm = warp >> 1, wn = warp & 1;
    const int g  = lane >> 2, t = lane & 3;

    const __half* Ab = A + (size_t)bm * 128 * DM;
    const __half* Bb = Bt + (size_t)bn * 128 * DM;

    float acc[4][8][4];
#pragma unroll
    for (int i = 0; i < 4; i++)
#pragma unroll
        for (int j = 0; j < 8; j++)
#pragma unroll
            for (int r = 0; r < 4; r++) acc[i][j][r] = 0.f;

    // ldsm per-thread address invariants (R9 mapping); B at +10240 in stage
    const uint32_t aBase = sbase +
        (uint32_t)(((wm * 64 + (lane & 15)) * GST + (lane >> 4) * 8) * 2);
    const int bmi = lane >> 3, br8 = lane & 7;
    const uint32_t bBase = sbase + 10240 +
        (uint32_t)(((wn * 64 + (bmi >> 1) * 8 + br8) * GST + (bmi & 1) * 8) * 2);

    auto load_chunk = [&](int kc, int buf) {
        const uint32_t s0 = sbase + buf * STG_B;
        // A: 128 rows x 32 halves = 512 x16B chunks; B same. 1024 chunks
        // total -> 8 cp.async per thread (c=0..3 A, c=4..7 B).
#pragma unroll
        for (int c = 0; c < 8; c++) {
            int id = tid + (c & 3) * 128;           // 0..511
            int row = id >> 2, c8 = (id & 3) * 8;
            if (c < 4) {
                cp16(s0 + (uint32_t)((row * GST + c8) * 2),
                     Ab + (size_t)row * DM + kc * 32 + c8);
            } else {
                cp16(s0 + 10240 + (uint32_t)((row * GST + c8) * 2),
                     Bb + (size_t)row * DM + kc * 32 + c8);
            }
        }
        cp_commit();
    };

    load_chunk(0, 0);
    load_chunk(1, 1);
#pragma unroll 1
    for (int kc = 0; kc < 32; kc++) {
        if (kc >= 30) cp_wait0(); else cp_wait1();   // chunk kc complete
        __syncthreads();   // protects buffer (kc+2)%3 (consumed at kc-1) + publishes loads
        if (kc < 30) load_chunk(kc + 2, (kc + 2) % 3);
        const uint32_t bufO = (uint32_t)((kc % 3) * STG_B);
#pragma unroll
        for (int ks = 0; ks < 2; ks++) {
            uint32_t af[4][4];
#pragma unroll
            for (int mt = 0; mt < 4; mt++)
                ldsm4(af[mt], aBase + bufO + mt * (16 * GST * 2) + ks * 32);
            uint32_t bf[4][4];
#pragma unroll
            for (int j = 0; j < 4; j++)
                ldsm4(bf[j], bBase + bufO + j * (16 * GST * 2) + ks * 32);
#pragma unroll
            for (int mt = 0; mt < 4; mt++)
#pragma unroll
                for (int nt = 0; nt < 8; nt++)
                    mma_f16(acc[mt][nt], af[mt], bf[nt >> 1] + (nt & 1) * 2);
        }
    }

#pragma unroll
    for (int mt = 0; mt < 4; mt++) {
        int r0 = bm * 128 + wm * 64 + mt * 16 + g;
#pragma unroll
        for (int nt = 0; nt < 8; nt++) {
            int c0 = bn * 128 + wn * 64 + nt * 8 + t * 2;
            float b0 = bias[c0], b1 = bias[c0 + 1];
            float v0 = acc[mt][nt][0] + b0;
            float v1 = acc[mt][nt][1] + b1;
            float v2 = acc[mt][nt][2] + b0;
            float v3 = acc[mt][nt][3] + b1;
            if (HALF_OUT) {
                __half* C = (__half*)Cout;
                *(__half2*)(C + (size_t)r0 * DM + c0)       = __floats2half2_rn(v0, v1);
                *(__half2*)(C + (size_t)(r0 + 8) * DM + c0) = __floats2half2_rn(v2, v3);
            } else {
                float* C = (float*)Cout;
                C[(size_t)r0 * DM + c0]           = v0;
                C[(size_t)r0 * DM + c0 + 1]       = v1;
                C[(size_t)(r0 + 8) * DM + c0]     = v2;
                C[(size_t)(r0 + 8) * DM + c0 + 1] = v3;
            }
        }
    }
}

__global__ __launch_bounds__(128) void qkv_gemm(
    const float* __restrict__ bq, const float* __restrict__ bk, const float* __restrict__ bv)
{
    int which = blockIdx.x >> 3;
    int bn = blockIdx.x & 7;
    const __half* W = g_wh + (size_t)which * DM * DM;
    const float* b = (which == 0) ? bq : (which == 1) ? bk : bv;
    __half* C = (which == 0) ? g_qh : (which == 1) ? g_kh : g_vh;
    gemm_body<true>(g_xh, W, b, C, bn, blockIdx.y);
}

__global__ __launch_bounds__(128) void out_gemm(
    const float* __restrict__ bo, float* __restrict__ out)
{
    gemm_body<false>(g_ch, g_wh + (size_t)3 * DM * DM, bo, out, blockIdx.x, blockIdx.y);
}

// ---------------- attention: one CTA (128 thr) per (b,h) — R9 verbatim ----
__device__ __forceinline__ float bias_at(int i, int j, const float* sBias) {
    int dr = (i >> 3) - (j >> 3) + 7;
    int df = (i & 7) - (j & 7) + 7;
    return sBias[dr * 15 + df];
}

#define AST 72   // half stride

__global__ __launch_bounds__(128, 5) void attn_kernel(const float* __restrict__ bias_table)
{
    __shared__ __align__(16) __half sQ[64 * AST];
    __shared__ __align__(16) __half sK[64 * AST];
    __shared__ __align__(16) __half sV[64 * AST];
    __shared__ float sBias[232];

    const int tid  = threadIdx.x;
    const int lane = tid & 31;
    const int warp = tid >> 5;
    const int g = lane >> 2, t = lane & 3;
    const int b = blockIdx.x >> 4, h = blockIdx.x & 15;

    const __half* qb = g_qh + (size_t)b * SEQ * DM + h * DK;
    const __half* kb = g_kh + (size_t)b * SEQ * DM + h * DK;
    const __half* vb = g_vh + (size_t)b * SEQ * DM + h * DK;

    for (int i = tid; i < 512; i += 128) {
        int s = i >> 3, c = i & 7;
        uint4 qv = ((const uint4*)(qb + (size_t)s * DM))[c];
        uint4 kv = ((const uint4*)(kb + (size_t)s * DM))[c];
        uint4 vv = ((const uint4*)(vb + (size_t)s * DM))[c];
        ((uint4*)(sQ + s * AST))[c] = qv;
        ((uint4*)(sK + s * AST))[c] = kv;
        ((uint4*)(sV + s * AST))[c] = vv;
    }
    for (int i = tid; i < 225; i += 128) sBias[i] = bias_table[i * 16 + h];
    __syncthreads();

    const uint32_t sQu = scvt(sQ), sKu = scvt(sK), sVu = scvt(sV);

    const uint32_t qBase = sQu + (uint32_t)(((warp * 16 + (lane & 15)) * AST + (lane >> 4) * 8) * 2);
    const int bmi = lane >> 3, br8 = lane & 7;
    const uint32_t kBase = sKu + (uint32_t)((((bmi >> 1) * 8 + br8) * AST + (bmi & 1) * 8) * 2);

    float acc[8][4];
#pragma unroll
    for (int nt = 0; nt < 8; nt++)
#pragma unroll
        for (int r = 0; r < 4; r++) acc[nt][r] = 0.f;

#pragma unroll
    for (int ks = 0; ks < 4; ks++) {
        uint32_t af[4];
        ldsm4(af, qBase + ks * 32);
#pragma unroll
        for (int j = 0; j < 4; j++) {
            uint32_t bf[4];
            ldsm4(bf, kBase + j * (16 * AST * 2) + ks * 32);
            mma_f16(acc[2 * j],     af, bf);
            mma_f16(acc[2 * j + 1], af, bf + 2);
        }
    }

    const float scale = 0.125f;
    const int i0 = warp * 16 + g;
    float mlo = -1e30f, mhi = -1e30f;
#pragma unroll
    for (int nt = 0; nt < 8; nt++) {
        int j0 = nt * 8 + t * 2;
        acc[nt][0] = acc[nt][0] * scale + bias_at(i0, j0, sBias);
        acc[nt][1] = acc[nt][1] * scale + bias_at(i0, j0 + 1, sBias);
        acc[nt][2] = acc[nt][2] * scale + bias_at(i0 + 8, j0, sBias);
        acc[nt][3] = acc[nt][3] * scale + bias_at(i0 + 8, j0 + 1, sBias);
        mlo = fmaxf(mlo, fmaxf(acc[nt][0], acc[nt][1]));
        mhi = fmaxf(mhi, fmaxf(acc[nt][2], acc[nt][3]));
    }
    mlo = fmaxf(mlo, __shfl_xor_sync(0xffffffffu, mlo, 1));
    mlo = fmaxf(mlo, __shfl_xor_sync(0xffffffffu, mlo, 2));
    mhi = fmaxf(mhi, __shfl_xor_sync(0xffffffffu, mhi, 1));
    mhi = fmaxf(mhi, __shfl_xor_sync(0xffffffffu, mhi, 2));
    float slo = 0.f, shi = 0.f;
#pragma unroll
    for (int nt = 0; nt < 8; nt++) {
        acc[nt][0] = __expf(acc[nt][0] - mlo);
        acc[nt][1] = __expf(acc[nt][1] - mlo);
        acc[nt][2] = __expf(acc[nt][2] - mhi);
        acc[nt][3] = __expf(acc[nt][3] - mhi);
        slo += acc[nt][0] + acc[nt][1];
        shi += acc[nt][2] + acc[nt][3];
    }
    slo += __shfl_xor_sync(0xffffffffu, slo, 1);
    slo += __shfl_xor_sync(0xffffffffu, slo, 2);
    shi += __shfl_xor_sync(0xffffffffu, shi, 1);
    shi += __shfl_xor_sync(0xffffffffu, shi, 2);
    const float ilo = 1.f / slo, ihi = 1.f / shi;

    uint32_t plo[8], phi[8];
#pragma unroll
    for (int nt = 0; nt < 8; nt++) {
        __half2 hl = __floats2half2_rn(acc[nt][0] * ilo, acc[nt][1] * ilo);
        __half2 hh = __floats2half2_rn(acc[nt][2] * ihi, acc[nt][3] * ihi);
        plo[nt] = *(uint32_t*)&hl;
        phi[nt] = *(uint32_t*)&hh;
    }

    __half* cb = g_ch + (size_t)b * SEQ * DM + h * DK;
#pragma unroll
    for (int nt = 0; nt < 8; nt++) {
        uint32_t v01[4], v23[4];
        ldsm4t(v01, sVu + (uint32_t)(((lane) * AST + nt * 8) * 2));
        ldsm4t(v23, sVu + (uint32_t)(((32 + lane) * AST + nt * 8) * 2));
        float o[4] = {0.f, 0.f, 0.f, 0.f};
#pragma unroll
        for (int ks = 0; ks < 4; ks++) {
            uint32_t af[4] = {plo[2 * ks], phi[2 * ks], plo[2 * ks + 1], phi[2 * ks + 1]};
            const uint32_t* bf = (ks < 2) ? (v01 + ks * 2) : (v23 + (ks - 2) * 2);
            mma_f16(o, af, bf);
        }
        int d0 = nt * 8 + t * 2;
        *(__half2*)(cb + (size_t)i0 * DM + d0)       = __floats2half2_rn(o[0], o[1]);
        *(__half2*)(cb + (size_t)(i0 + 8) * DM + d0) = __floats2half2_rn(o[2], o[3]);
    }
}

// ---------------- launch ----------------
extern "C" void kernel_launch(void* const* d_in, const int* in_sizes, int n_in,
                              void* d_out, int out_size)
{
    const float* x  = (const float*)d_in[0];
    const float* Wq = (const float*)d_in[1];
    const float* bq = (const float*)d_in[2];
    const float* Wk = (const float*)d_in[3];
    const float* bk = (const float*)d_in[4];
    const float* Wv = (const float*)d_in[5];
    const float* bv = (const float*)d_in[6];
    const float* Wo = (const float*)d_in[7];
    const float* bo = (const float*)d_in[8];
    const float* bt = (const float*)d_in[9];
    float* out = (float*)d_out;

    cudaFuncSetAttribute(qkv_gemm, cudaFuncAttributeMaxDynamicSharedMemorySize, GEMM_SMEM);
    cudaFuncSetAttribute(out_gemm, cudaFuncAttributeMaxDynamicSharedMemorySize, GEMM_SMEM);

    half_x<<<16384, 256>>>(x);
    half_wT<<<dim3(32, 32, 4), dim3(32, 8)>>>(Wq, Wk, Wv, Wo);
    qkv_gemm<<<dim3(24, 512), 128, GEMM_SMEM>>>(bq, bk, bv);
    attn_kernel<<<16384, 128>>>(bt);
    out_gemm<<<dim3(8, 512), 128, GEMM_SMEM>>>(bo, out);
}

// round 15
// speedup vs baseline: 1.5687x; 1.1086x over previous
#include <cuda_runtime.h>
#include <cuda_fp16.h>
#include <cstdint>
#include <cstddef>

// ---------------------------------------------------------------------------
// MHSA B=1024 S=64 D=1024 H=16 dk=64.
// R15: GEMM = R9 verbatim (128x128 CTA, 4 warps of 64x64, stride-40 static
// smem, 2-stage cp.async, ldmatrix, fp16 m16n8k16) — proven 1663us config;
// R13/R14 showed deeper pipelines lose to its occupancy. Changes:
//   1) attn: V loaded via cp.async overlapping scores+softmax (front LDG
//      batch 12->8), wait_group 0 before P@V.
//   2) prepasses merged into one kernel (x-convert + W-transpose).
// ---------------------------------------------------------------------------

#define M_TOT   65536
#define DM      1024
#define SEQ     64
#define DK      64

__device__ __half g_xh[(size_t)M_TOT * DM];
__device__ __half g_wh[(size_t)4 * DM * DM];      // fp16 W^T: [mat][n][k]
__device__ __half g_qh[(size_t)M_TOT * DM];
__device__ __half g_kh[(size_t)M_TOT * DM];
__device__ __half g_vh[(size_t)M_TOT * DM];
__device__ __half g_ch[(size_t)M_TOT * DM];

// ---------------- PTX helpers ----------------
__device__ __forceinline__ void mma_f16(float* d, const uint32_t* a, const uint32_t* b) {
    asm volatile(
        "mma.sync.aligned.m16n8k16.row.col.f32.f16.f16.f32 "
        "{%0,%1,%2,%3}, {%4,%5,%6,%7}, {%8,%9}, {%0,%1,%2,%3};"
        : "+f"(d[0]), "+f"(d[1]), "+f"(d[2]), "+f"(d[3])
        : "r"(a[0]), "r"(a[1]), "r"(a[2]), "r"(a[3]), "r"(b[0]), "r"(b[1]));
}
__device__ __forceinline__ void ldsm4(uint32_t* r, uint32_t a) {
    asm volatile("ldmatrix.sync.aligned.m8n8.x4.shared.b16 {%0,%1,%2,%3}, [%4];"
                 : "=r"(r[0]), "=r"(r[1]), "=r"(r[2]), "=r"(r[3]) : "r"(a));
}
__device__ __forceinline__ void ldsm4t(uint32_t* r, uint32_t a) {
    asm volatile("ldmatrix.sync.aligned.m8n8.x4.trans.shared.b16 {%0,%1,%2,%3}, [%4];"
                 : "=r"(r[0]), "=r"(r[1]), "=r"(r[2]), "=r"(r[3]) : "r"(a));
}
__device__ __forceinline__ void cp16(uint32_t s, const void* g) {
    asm volatile("cp.async.ca.shared.global [%0], [%1], 16;" :: "r"(s), "l"(g));
}
__device__ __forceinline__ void cp_commit() { asm volatile("cp.async.commit_group;"); }
__device__ __forceinline__ void cp_wait0()  { asm volatile("cp.async.wait_group 0;"); }
__device__ __forceinline__ uint32_t scvt(const void* p) {
    return (uint32_t)__cvta_generic_to_shared(p);
}

// ---------------- merged prepass: X->fp16 and W->W^T fp16 ----------------
// blocks [0,16384): convert X (1024 float4 each)
// blocks [16384,20480): transpose one 32x32 tile of one W matrix
__global__ __launch_bounds__(256) void prep(
    const float* __restrict__ x,
    const float* __restrict__ Wq, const float* __restrict__ Wk,
    const float* __restrict__ Wv, const float* __restrict__ Wo)
{
    __shared__ __half tbuf[32][33];
    const int tid = threadIdx.x;
    if (blockIdx.x < 16384) {
        const float4* src = (const float4*)x;
        uint2* dst = (uint2*)g_xh;
#pragma unroll
        for (int j = 0; j < 4; j++) {
            size_t i = (size_t)blockIdx.x * 1024 + j * 256 + tid;
            float4 v = src[i];
            __half2 lo = __floats2half2_rn(v.x, v.y);
            __half2 hi = __floats2half2_rn(v.z, v.w);
            uint2 o;
            o.x = *(uint32_t*)&lo;
            o.y = *(uint32_t*)&hi;
            dst[i] = o;
        }
    } else {
        const int bid = blockIdx.x - 16384;          // 0..4095
        const int z = bid >> 10;                     // matrix select
        const int r = bid & 1023;                    // 32x32 tile
        const float* src = (z == 0) ? Wq : (z == 1) ? Wk : (z == 2) ? Wv : Wo;
        __half* dst = g_wh + (size_t)z * DM * DM;
        const int tx = tid & 31, ty = tid >> 5;      // 32 x 8
        const int bx = (r & 31) * 32, by = (r >> 5) * 32;
#pragma unroll
        for (int j = 0; j < 4; j++)
            tbuf[ty + 8 * j][tx] = __float2half(src[(size_t)(by + ty + 8 * j) * DM + bx + tx]);
        __syncthreads();
#pragma unroll
        for (int j = 0; j < 4; j++)
            dst[(size_t)(bx + ty + 8 * j) * DM + by + tx] = tbuf[tx][ty + 8 * j];
    }
}

// ---------------- GEMM: C[128x128] = A[.,1024] @ W^T[n][k] + bias ----------
// R9 verbatim: 128 threads = 4 warps (2m x 2n), warp tile 64x64, BK=32,
// stride 40 halves, 2-stage static smem.
#define GST 40   // half stride

template <bool HALF_OUT>
__device__ __forceinline__ void gemm_body(
    const __half* __restrict__ A, const __half* __restrict__ Bt,
    const float* __restrict__ bias, void* __restrict__ Cout,
    int bn, int bm)
{
    __shared__ __align__(16) __half sA[2][128 * GST];
    __shared__ __align__(16) __half sB[2][128 * GST];

    const int tid  = threadIdx.x;
    const int lane = tid & 31;
    const int warp = tid >> 5;
    const int wm = warp >> 1, wn = warp & 1;
    const int g  = lane >> 2, t = lane & 3;

    const __half* Ab = A + (size_t)bm * 128 * DM;
    const __half* Bb = Bt + (size_t)bn * 128 * DM;

    float acc[4][8][4];
#pragma unroll
    for (int i = 0; i < 4; i++)
#pragma unroll
        for (int j = 0; j < 8; j++)
#pragma unroll
            for (int r = 0; r < 4; r++) acc[i][j][r] = 0.f;

    const uint32_t sAu = scvt(sA);
    const uint32_t sBu = scvt(sB);

    const uint32_t aBase = sAu + (uint32_t)(((wm * 64 + (lane & 15)) * GST + (lane >> 4) * 8) * 2);
    const int bmi = lane >> 3, br8 = lane & 7;
    const uint32_t bBase = sBu + (uint32_t)(((wn * 64 + (bmi >> 1) * 8 + br8) * GST + (bmi & 1) * 8) * 2);

    auto load_chunk = [&](int kc, int buf) {
        const uint32_t aS = sAu + buf * (128 * GST * 2);
        const uint32_t bS = sBu + buf * (128 * GST * 2);
#pragma unroll
        for (int c = 0; c < 4; c++) {
            int id = tid + c * 128;                 // 0..511
            int row = id >> 2, c8 = (id & 3) * 8;
            cp16(aS + (uint32_t)((row * GST + c8) * 2), Ab + (size_t)row * DM + kc * 32 + c8);
            cp16(bS + (uint32_t)((row * GST + c8) * 2), Bb + (size_t)row * DM + kc * 32 + c8);
        }
        cp_commit();
    };

    load_chunk(0, 0);
#pragma unroll 1
    for (int kc = 0; kc < 32; kc++) {
        cp_wait0();
        __syncthreads();
        if (kc < 31) load_chunk(kc + 1, (kc + 1) & 1);
        const uint32_t bufO = (kc & 1) * (128 * GST * 2);
#pragma unroll
        for (int ks = 0; ks < 2; ks++) {
            uint32_t af[4][4];
#pragma unroll
            for (int mt = 0; mt < 4; mt++)
                ldsm4(af[mt], aBase + bufO + mt * (16 * GST * 2) + ks * 32);
            uint32_t bf[4][4];
#pragma unroll
            for (int j = 0; j < 4; j++)
                ldsm4(bf[j], bBase + bufO + j * (16 * GST * 2) + ks * 32);
#pragma unroll
            for (int mt = 0; mt < 4; mt++)
#pragma unroll
                for (int nt = 0; nt < 8; nt++)
                    mma_f16(acc[mt][nt], af[mt], bf[nt >> 1] + (nt & 1) * 2);
        }
        __syncthreads();
    }

#pragma unroll
    for (int mt = 0; mt < 4; mt++) {
        int r0 = bm * 128 + wm * 64 + mt * 16 + g;
#pragma unroll
        for (int nt = 0; nt < 8; nt++) {
            int c0 = bn * 128 + wn * 64 + nt * 8 + t * 2;
            float b0 = bias[c0], b1 = bias[c0 + 1];
            float v0 = acc[mt][nt][0] + b0;
            float v1 = acc[mt][nt][1] + b1;
            float v2 = acc[mt][nt][2] + b0;
            float v3 = acc[mt][nt][3] + b1;
            if (HALF_OUT) {
                __half* C = (__half*)Cout;
                *(__half2*)(C + (size_t)r0 * DM + c0)       = __floats2half2_rn(v0, v1);
                *(__half2*)(C + (size_t)(r0 + 8) * DM + c0) = __floats2half2_rn(v2, v3);
            } else {
                float* C = (float*)Cout;
                C[(size_t)r0 * DM + c0]           = v0;
                C[(size_t)r0 * DM + c0 + 1]       = v1;
                C[(size_t)(r0 + 8) * DM + c0]     = v2;
                C[(size_t)(r0 + 8) * DM + c0 + 1] = v3;
            }
        }
    }
}

__global__ __launch_bounds__(128) void qkv_gemm(
    const float* __restrict__ bq, const float* __restrict__ bk, const float* __restrict__ bv)
{
    int which = blockIdx.x >> 3;
    int bn = blockIdx.x & 7;
    const __half* W = g_wh + (size_t)which * DM * DM;
    const float* b = (which == 0) ? bq : (which == 1) ? bk : bv;
    __half* C = (which == 0) ? g_qh : (which == 1) ? g_kh : g_vh;
    gemm_body<true>(g_xh, W, b, C, bn, blockIdx.y);
}

__global__ __launch_bounds__(128) void out_gemm(
    const float* __restrict__ bo, float* __restrict__ out)
{
    gemm_body<false>(g_ch, g_wh + (size_t)3 * DM * DM, bo, out, blockIdx.x, blockIdx.y);
}

// ---------------- attention: one CTA (128 thr) per (b,h) ----------------
// V arrives via cp.async overlapped with scores+softmax; Q/K loaded sync.
__device__ __forceinline__ float bias_at(int i, int j, const float* sBias) {
    int dr = (i >> 3) - (j >> 3) + 7;
    int df = (i & 7) - (j & 7) + 7;
    return sBias[dr * 15 + df];
}

#define AST 72   // half stride

__global__ __launch_bounds__(128, 5) void attn_kernel(const float* __restrict__ bias_table)
{
    __shared__ __align__(16) __half sQ[64 * AST];
    __shared__ __align__(16) __half sK[64 * AST];
    __shared__ __align__(16) __half sV[64 * AST];
    __shared__ float sBias[232];

    const int tid  = threadIdx.x;
    const int lane = tid & 31;
    const int warp = tid >> 5;
    const int g = lane >> 2, t = lane & 3;
    const int b = blockIdx.x >> 4, h = blockIdx.x & 15;

    const __half* qb = g_qh + (size_t)b * SEQ * DM + h * DK;
    const __half* kb = g_kh + (size_t)b * SEQ * DM + h * DK;
    const __half* vb = g_vh + (size_t)b * SEQ * DM + h * DK;

    const uint32_t sQu = scvt(sQ), sKu = scvt(sK), sVu = scvt(sV);

    // V via cp.async (latency overlapped with scores+softmax below)
#pragma unroll
    for (int c = 0; c < 4; c++) {
        int id = tid + c * 128;                  // 0..511
        int s = id >> 3, ch = id & 7;
        cp16(sVu + (uint32_t)((s * AST + ch * 8) * 2), vb + (size_t)s * DM + ch * 8);
    }
    cp_commit();

    // Q, K synchronous
    for (int i = tid; i < 512; i += 128) {
        int s = i >> 3, c = i & 7;
        uint4 qv = ((const uint4*)(qb + (size_t)s * DM))[c];
        uint4 kv = ((const uint4*)(kb + (size_t)s * DM))[c];
        ((uint4*)(sQ + s * AST))[c] = qv;
        ((uint4*)(sK + s * AST))[c] = kv;
    }
    for (int i = tid; i < 225; i += 128) sBias[i] = bias_table[i * 16 + h];
    __syncthreads();   // Q, K, bias visible

    const uint32_t qBase = sQu + (uint32_t)(((warp * 16 + (lane & 15)) * AST + (lane >> 4) * 8) * 2);
    const int bmi = lane >> 3, br8 = lane & 7;
    const uint32_t kBase = sKu + (uint32_t)((((bmi >> 1) * 8 + br8) * AST + (bmi & 1) * 8) * 2);

    float acc[8][4];
#pragma unroll
    for (int nt = 0; nt < 8; nt++)
#pragma unroll
        for (int r = 0; r < 4; r++) acc[nt][r] = 0.f;

#pragma unroll
    for (int ks = 0; ks < 4; ks++) {
        uint32_t af[4];
        ldsm4(af, qBase + ks * 32);
#pragma unroll
        for (int j = 0; j < 4; j++) {
            uint32_t bf[4];
            ldsm4(bf, kBase + j * (16 * AST * 2) + ks * 32);
            mma_f16(acc[2 * j],     af, bf);
            mma_f16(acc[2 * j + 1], af, bf + 2);
        }
    }

    const float scale = 0.125f;
    const int i0 = warp * 16 + g;
    float mlo = -1e30f, mhi = -1e30f;
#pragma unroll
    for (int nt = 0; nt < 8; nt++) {
        int j0 = nt * 8 + t * 2;
        acc[nt][0] = acc[nt][0] * scale + bias_at(i0, j0, sBias);
        acc[nt][1] = acc[nt][1] * scale + bias_at(i0, j0 + 1, sBias);
        acc[nt][2] = acc[nt][2] * scale + bias_at(i0 + 8, j0, sBias);
        acc[nt][3] = acc[nt][3] * scale + bias_at(i0 + 8, j0 + 1, sBias);
        mlo = fmaxf(mlo, fmaxf(acc[nt][0], acc[nt][1]));
        mhi = fmaxf(mhi, fmaxf(acc[nt][2], acc[nt][3]));
    }
    mlo = fmaxf(mlo, __shfl_xor_sync(0xffffffffu, mlo, 1));
    mlo = fmaxf(mlo, __shfl_xor_sync(0xffffffffu, mlo, 2));
    mhi = fmaxf(mhi, __shfl_xor_sync(0xffffffffu, mhi, 1));
    mhi = fmaxf(mhi, __shfl_xor_sync(0xffffffffu, mhi, 2));
    float slo = 0.f, shi = 0.f;
#pragma unroll
    for (int nt = 0; nt < 8; nt++) {
        acc[nt][0] = __expf(acc[nt][0] - mlo);
        acc[nt][1] = __expf(acc[nt][1] - mlo);
        acc[nt][2] = __expf(acc[nt][2] - mhi);
        acc[nt][3] = __expf(acc[nt][3] - mhi);
        slo += acc[nt][0] + acc[nt][1];
        shi += acc[nt][2] + acc[nt][3];
    }
    slo += __shfl_xor_sync(0xffffffffu, slo, 1);
    slo += __shfl_xor_sync(0xffffffffu, slo, 2);
    shi += __shfl_xor_sync(0xffffffffu, shi, 1);
    shi += __shfl_xor_sync(0xffffffffu, shi, 2);
    const float ilo = 1.f / slo, ihi = 1.f / shi;

    uint32_t plo[8], phi[8];
#pragma unroll
    for (int nt = 0; nt < 8; nt++) {
        __half2 hl = __floats2half2_rn(acc[nt][0] * ilo, acc[nt][1] * ilo);
        __half2 hh = __floats2half2_rn(acc[nt][2] * ihi, acc[nt][3] * ihi);
        plo[nt] = *(uint32_t*)&hl;
        phi[nt] = *(uint32_t*)&hh;
    }

    // V must be resident before ldmatrix reads it
    cp_wait0();
    __syncthreads();

    __half* cb = g_ch + (size_t)b * SEQ * DM + h * DK;
#pragma unroll
    for (int nt = 0; nt < 8; nt++) {
        uint32_t v01[4], v23[4];
        ldsm4t(v01, sVu + (uint32_t)(((lane) * AST + nt * 8) * 2));
        ldsm4t(v23, sVu + (uint32_t)(((32 + lane) * AST + nt * 8) * 2));
        float o[4] = {0.f, 0.f, 0.f, 0.f};
#pragma unroll
        for (int ks = 0; ks < 4; ks++) {
            uint32_t af[4] = {plo[2 * ks], phi[2 * ks], plo[2 * ks + 1], phi[2 * ks + 1]};
            const uint32_t* bf = (ks < 2) ? (v01 + ks * 2) : (v23 + (ks - 2) * 2);
            mma_f16(o, af, bf);
        }
        int d0 = nt * 8 + t * 2;
        *(__half2*)(cb + (size_t)i0 * DM + d0)       = __floats2half2_rn(o[0], o[1]);
        *(__half2*)(cb + (size_t)(i0 + 8) * DM + d0) = __floats2half2_rn(o[2], o[3]);
    }
}

// ---------------- launch ----------------
extern "C" void kernel_launch(void* const* d_in, const int* in_sizes, int n_in,
                              void* d_out, int out_size)
{
    const float* x  = (const float*)d_in[0];
    const float* Wq = (const float*)d_in[1];
    const float* bq = (const float*)d_in[2];
    const float* Wk = (const float*)d_in[3];
    const float* bk = (const float*)d_in[4];
    const float* Wv = (const float*)d_in[5];
    const float* bv = (const float*)d_in[6];
    const float* Wo = (const float*)d_in[7];
    const float* bo = (const float*)d_in[8];
    const float* bt = (const float*)d_in[9];
    float* out = (float*)d_out;

    prep<<<20480, 256>>>(x, Wq, Wk, Wv, Wo);
    qkv_gemm<<<dim3(24, 512), 128>>>(bq, bk, bv);
    attn_kernel<<<16384, 128>>>(bt);
    out_gemm<<<dim3(8, 512), 128>>>(bo, out);
}